// round 2
// baseline (speedup 1.0000x reference)
#include <cuda_runtime.h>

typedef unsigned long long ull;

#define N_ROWS 1024   // N
#define P_PIX  1024   // P
#define E_DIM  512    // ENC / TAG / LANG
#define A_DIM  256    // ATT

// Scratch
__device__ float g_att1 [P_PIX * A_DIM];    // (P, A)
__device__ float g_att23[N_ROWS * A_DIM];   // (N, A) = att2+att3 (bias folded)
__device__ float g_att  [N_ROWS * P_PIX];   // (N, P)

// ---- packed f32x2 helpers ----
#define FMA2(acc, a, b) \
    asm("fma.rn.f32x2 %0, %1, %2, %0;" : "+l"(acc) : "l"(a), "l"(b))

#define RELU_FMA2(acc, x1, x2, w)                         \
    asm("{\n\t"                                           \
        ".reg .f32 rlo, rhi;\n\t"                         \
        ".reg .b64 rt;\n\t"                               \
        "add.rn.f32x2 rt, %1, %2;\n\t"                    \
        "mov.b64 {rlo, rhi}, rt;\n\t"                     \
        "max.f32 rlo, rlo, 0f00000000;\n\t"               \
        "max.f32 rhi, rhi, 0f00000000;\n\t"               \
        "mov.b64 rt, {rlo, rhi};\n\t"                     \
        "fma.rn.f32x2 %0, rt, %3, %0;\n\t"                \
        "}" : "+l"(acc) : "l"(x1), "l"(x2), "l"(w))

#define UNPACK2(l, h, v) \
    asm("mov.b64 {%0, %1}, %2;" : "=f"(l), "=f"(h) : "l"(v))

// ---------------------------------------------------------------------------
// Kernel 1: projection GEMMs, C = A @ B^T + bias
//   z=0: g_att1  = enc @ We^T + be                (M=1024(P), N=256, K=512)
//   z=1: g_att23 = dh @ Wt^T + lo @ Wl^T + bt+bl  (M=1024(N), N=256, K=1024)
// BM=32, BN=64, BK=16, 128 threads, 4m x 4n microtile (packed over m).
// ---------------------------------------------------------------------------
__global__ __launch_bounds__(128)
void gemm_attproj(const float* __restrict__ enc, const float* __restrict__ We, const float* __restrict__ be,
                  const float* __restrict__ dh,  const float* __restrict__ Wt, const float* __restrict__ bt,
                  const float* __restrict__ lo,  const float* __restrict__ Wl, const float* __restrict__ bl)
{
    __shared__ float As [16][36];    // [k][m] transposed, pairs along m
    __shared__ float Bsd[16][132];   // [k][2n] duplicated {b,b}

    const int tid = threadIdx.x;
    const int z   = blockIdx.z;
    const int m0  = blockIdx.y * 32;
    const int n0  = blockIdx.x * 64;

    const int lm  = tid >> 2;         // 0..31 (A loader row)
    const int lkc = (tid & 3) * 4;    // k sub-chunk
    const int bn  = tid >> 1;         // 0..63 (B loader row)
    const int bkc = (tid & 1) * 8;

    const int tn  = tid & 15;         // n-group (4 each)
    const int tm  = tid >> 4;         // 0..7 m-group (4 each)

    ull acc[2][4] = {};               // [m-pair][n]

    const int nseg = (z == 0) ? 1 : 2;
    for (int s = 0; s < nseg; s++) {
        const float* A = (z == 0) ? enc : (s == 0 ? dh : lo);
        const float* B = (z == 0) ? We  : (s == 0 ? Wt : Wl);
        for (int k0 = 0; k0 < E_DIM; k0 += 16) {
            __syncthreads();
            // stage A (32m x 16k), transpose to [k][m]
            float4 av = *(const float4*)&A[(m0 + lm) * E_DIM + k0 + lkc];
            As[lkc + 0][lm] = av.x;
            As[lkc + 1][lm] = av.y;
            As[lkc + 2][lm] = av.z;
            As[lkc + 3][lm] = av.w;
            // stage B (64n x 16k), duplicated to [k][2n]
            {
                const float* Brow = &B[(n0 + bn) * E_DIM + k0 + bkc];
                float4 b0 = *(const float4*)&Brow[0];
                float4 b1 = *(const float4*)&Brow[4];
                *(float2*)&Bsd[bkc + 0][2 * bn] = make_float2(b0.x, b0.x);
                *(float2*)&Bsd[bkc + 1][2 * bn] = make_float2(b0.y, b0.y);
                *(float2*)&Bsd[bkc + 2][2 * bn] = make_float2(b0.z, b0.z);
                *(float2*)&Bsd[bkc + 3][2 * bn] = make_float2(b0.w, b0.w);
                *(float2*)&Bsd[bkc + 4][2 * bn] = make_float2(b1.x, b1.x);
                *(float2*)&Bsd[bkc + 5][2 * bn] = make_float2(b1.y, b1.y);
                *(float2*)&Bsd[bkc + 6][2 * bn] = make_float2(b1.z, b1.z);
                *(float2*)&Bsd[bkc + 7][2 * bn] = make_float2(b1.w, b1.w);
            }
            __syncthreads();
            #pragma unroll
            for (int kk = 0; kk < 16; kk++) {
                ulonglong2 ap  = *(const ulonglong2*)&As [kk][tm * 4];
                ulonglong2 b01 = *(const ulonglong2*)&Bsd[kk][tn * 8];
                ulonglong2 b23 = *(const ulonglong2*)&Bsd[kk][tn * 8 + 4];
                FMA2(acc[0][0], ap.x, b01.x); FMA2(acc[0][1], ap.x, b01.y);
                FMA2(acc[0][2], ap.x, b23.x); FMA2(acc[0][3], ap.x, b23.y);
                FMA2(acc[1][0], ap.y, b01.x); FMA2(acc[1][1], ap.y, b01.y);
                FMA2(acc[1][2], ap.y, b23.x); FMA2(acc[1][3], ap.y, b23.y);
            }
        }
    }

    float bias[4];
    #pragma unroll
    for (int j = 0; j < 4; j++) {
        int c = n0 + tn * 4 + j;
        bias[j] = (z == 0) ? be[c] : (bt[c] + bl[c]);
    }
    float* C = (z == 0) ? g_att1 : g_att23;
    #pragma unroll
    for (int mp = 0; mp < 2; mp++) {
        float l0, h0, l1, h1, l2, h2, l3, h3;
        UNPACK2(l0, h0, acc[mp][0]);
        UNPACK2(l1, h1, acc[mp][1]);
        UNPACK2(l2, h2, acc[mp][2]);
        UNPACK2(l3, h3, acc[mp][3]);
        int row = m0 + tm * 4 + mp * 2;
        *(float4*)&C[row * A_DIM + n0 + tn * 4] =
            make_float4(l0 + bias[0], l1 + bias[1], l2 + bias[2], l3 + bias[3]);
        *(float4*)&C[(row + 1) * A_DIM + n0 + tn * 4] =
            make_float4(h0 + bias[0], h1 + bias[1], h2 + bias[2], h3 + bias[3]);
    }
}

// ---------------------------------------------------------------------------
// Kernel 2: att[n,p] = sum_a relu(att1[p,a] + att23[n,a]) * Wf[a]
// (bf cancels in softmax). 64n x 64p tile, 256 threads, packed f32x2.
// ---------------------------------------------------------------------------
__global__ __launch_bounds__(256)
void att_main_v2(const float* __restrict__ Wf)
{
    __shared__ float s1  [32][68];    // [a][p]
    __shared__ float s23d[32][132];   // [a][2n] duplicated
    __shared__ float swd [2 * A_DIM]; // Wf duplicated

    const int tid = threadIdx.x;
    const int tx  = tid & 15;         // p-group (4 each)
    const int ty  = tid >> 4;         // n-group (4 each)
    const int p0  = blockIdx.x * 64;
    const int n0  = blockIdx.y * 64;

    if (tid < A_DIM) {
        float w = Wf[tid];
        *(float2*)&swd[2 * tid] = make_float2(w, w);
    }

    ull acc[4][2] = {};               // [n j][p-pair]

    for (int a0 = 0; a0 < A_DIM; a0 += 32) {
        __syncthreads();
        #pragma unroll
        for (int i = 0; i < 8; i++) {
            int e = tid + 256 * i;
            int a = e & 31, r = e >> 5;
            s1[a][r] = g_att1[(p0 + r) * A_DIM + a0 + a];
            float v  = g_att23[(n0 + r) * A_DIM + a0 + a];
            *(float2*)&s23d[a][2 * r] = make_float2(v, v);
        }
        __syncthreads();

        #pragma unroll 4
        for (int a = 0; a < 32; a++) {
            ulonglong2 x1  = *(const ulonglong2*)&s1  [a][tx * 4];
            ulonglong2 x2a = *(const ulonglong2*)&s23d[a][ty * 8];
            ulonglong2 x2b = *(const ulonglong2*)&s23d[a][ty * 8 + 4];
            ull w = *(const ull*)&swd[2 * (a0 + a)];
            RELU_FMA2(acc[0][0], x1.x, x2a.x, w); RELU_FMA2(acc[0][1], x1.y, x2a.x, w);
            RELU_FMA2(acc[1][0], x1.x, x2a.y, w); RELU_FMA2(acc[1][1], x1.y, x2a.y, w);
            RELU_FMA2(acc[2][0], x1.x, x2b.x, w); RELU_FMA2(acc[2][1], x1.y, x2b.x, w);
            RELU_FMA2(acc[3][0], x1.x, x2b.y, w); RELU_FMA2(acc[3][1], x1.y, x2b.y, w);
        }
    }

    #pragma unroll
    for (int j = 0; j < 4; j++) {
        float l0, h0, l1, h1;
        UNPACK2(l0, h0, acc[j][0]);
        UNPACK2(l1, h1, acc[j][1]);
        *(float4*)&g_att[(n0 + ty * 4 + j) * P_PIX + p0 + tx * 4] =
            make_float4(l0, h0, l1, h1);
    }
}

// ---------------------------------------------------------------------------
// Kernel 3: row softmax over P -> alpha
// ---------------------------------------------------------------------------
__global__ __launch_bounds__(256)
void softmax_kernel(float* __restrict__ alpha)
{
    const int n   = blockIdx.x;
    const int tid = threadIdx.x;
    const float* row = g_att + n * P_PIX;

    __shared__ float wred[8];
    __shared__ float bm, bs;

    float x[4];
    float m = -1e30f;
    #pragma unroll
    for (int i = 0; i < 4; i++) {
        x[i] = row[tid + 256 * i];
        m = fmaxf(m, x[i]);
    }
    #pragma unroll
    for (int o = 16; o > 0; o >>= 1) m = fmaxf(m, __shfl_xor_sync(0xffffffffu, m, o));
    if ((tid & 31) == 0) wred[tid >> 5] = m;
    __syncthreads();
    if (tid == 0) {
        float v = wred[0];
        #pragma unroll
        for (int k = 1; k < 8; k++) v = fmaxf(v, wred[k]);
        bm = v;
    }
    __syncthreads();
    m = bm;

    float s = 0.0f;
    #pragma unroll
    for (int i = 0; i < 4; i++) {
        x[i] = __expf(x[i] - m);
        s += x[i];
    }
    #pragma unroll
    for (int o = 16; o > 0; o >>= 1) s += __shfl_xor_sync(0xffffffffu, s, o);
    __syncthreads();
    if ((tid & 31) == 0) wred[tid >> 5] = s;
    __syncthreads();
    if (tid == 0) {
        float v = 0.0f;
        #pragma unroll
        for (int k = 0; k < 8; k++) v += wred[k];
        bs = v;
    }
    __syncthreads();
    float inv = 1.0f / bs;

    #pragma unroll
    for (int i = 0; i < 4; i++)
        alpha[n * P_PIX + tid + 256 * i] = x[i] * inv;
}

// ---------------------------------------------------------------------------
// Kernel 4: awe = alpha @ enc   (M=1024, N=512, K=1024)
// BM=32, BN=64, BK=16, 128 threads, 4m x 4n microtile packed over m.
// ---------------------------------------------------------------------------
__global__ __launch_bounds__(128)
void gemm_ab_v2(const float* __restrict__ A,   // alpha (N, P)
                const float* __restrict__ B,   // enc   (P, E)
                float* __restrict__ C)         // awe   (N, E)
{
    __shared__ float As [16][36];
    __shared__ float Bsd[16][132];

    const int tid = threadIdx.x;
    const int m0  = blockIdx.y * 32;
    const int n0  = blockIdx.x * 64;

    const int lm  = tid >> 2;
    const int lkc = (tid & 3) * 4;
    const int tn  = tid & 15;
    const int tm  = tid >> 4;

    ull acc[2][4] = {};

    for (int k0 = 0; k0 < P_PIX; k0 += 16) {
        __syncthreads();
        float4 av = *(const float4*)&A[(m0 + lm) * P_PIX + k0 + lkc];
        As[lkc + 0][lm] = av.x;
        As[lkc + 1][lm] = av.y;
        As[lkc + 2][lm] = av.z;
        As[lkc + 3][lm] = av.w;
        #pragma unroll
        for (int i = 0; i < 8; i++) {
            int e = tid + 128 * i;
            int k = e >> 6, nn = e & 63;
            float v = B[(k0 + k) * E_DIM + n0 + nn];
            *(float2*)&Bsd[k][2 * nn] = make_float2(v, v);
        }
        __syncthreads();
        #pragma unroll
        for (int kk = 0; kk < 16; kk++) {
            ulonglong2 ap  = *(const ulonglong2*)&As [kk][tm * 4];
            ulonglong2 b01 = *(const ulonglong2*)&Bsd[kk][tn * 8];
            ulonglong2 b23 = *(const ulonglong2*)&Bsd[kk][tn * 8 + 4];
            FMA2(acc[0][0], ap.x, b01.x); FMA2(acc[0][1], ap.x, b01.y);
            FMA2(acc[0][2], ap.x, b23.x); FMA2(acc[0][3], ap.x, b23.y);
            FMA2(acc[1][0], ap.y, b01.x); FMA2(acc[1][1], ap.y, b01.y);
            FMA2(acc[1][2], ap.y, b23.x); FMA2(acc[1][3], ap.y, b23.y);
        }
    }

    #pragma unroll
    for (int mp = 0; mp < 2; mp++) {
        float l0, h0, l1, h1, l2, h2, l3, h3;
        UNPACK2(l0, h0, acc[mp][0]);
        UNPACK2(l1, h1, acc[mp][1]);
        UNPACK2(l2, h2, acc[mp][2]);
        UNPACK2(l3, h3, acc[mp][3]);
        int row = m0 + tm * 4 + mp * 2;
        *(float4*)&C[row * E_DIM + n0 + tn * 4]       = make_float4(l0, l1, l2, l3);
        *(float4*)&C[(row + 1) * E_DIM + n0 + tn * 4] = make_float4(h0, h1, h2, h3);
    }
}

// ---------------------------------------------------------------------------
// Launch
// ---------------------------------------------------------------------------
extern "C" void kernel_launch(void* const* d_in, const int* in_sizes, int n_in,
                              void* d_out, int out_size)
{
    (void)in_sizes; (void)n_in; (void)out_size;
    const float* enc = (const float*)d_in[0];
    const float* dh  = (const float*)d_in[1];
    const float* lo  = (const float*)d_in[2];
    const float* We  = (const float*)d_in[3];
    const float* be  = (const float*)d_in[4];
    const float* Wt  = (const float*)d_in[5];
    const float* bt  = (const float*)d_in[6];
    const float* Wl  = (const float*)d_in[7];
    const float* bl  = (const float*)d_in[8];
    const float* Wf  = (const float*)d_in[9];
    // d_in[10] = bf: cancels in softmax.

    float* awe   = (float*)d_out;
    float* alpha = (float*)d_out + N_ROWS * E_DIM;

    dim3 g1(A_DIM / 64, 1024 / 32, 2);
    gemm_attproj<<<g1, 128>>>(enc, We, be, dh, Wt, bt, lo, Wl, bl);

    dim3 g2(P_PIX / 64, N_ROWS / 64);
    att_main_v2<<<g2, 256>>>(Wf);

    softmax_kernel<<<N_ROWS, 256>>>(alpha);

    dim3 g4(E_DIM / 64, N_ROWS / 32);
    gemm_ab_v2<<<g4, 128>>>(alpha, enc, awe);
}

// round 3
// speedup vs baseline: 1.8614x; 1.8614x over previous
#include <cuda_runtime.h>

#define N_ROWS 1024   // N
#define P_PIX  1024   // P
#define E_DIM  512    // ENC / TAG / LANG
#define A_DIM  256    // ATT

// Scratch
__device__ float g_att1 [P_PIX * A_DIM];    // (P, A)
__device__ float g_att23[N_ROWS * A_DIM];   // (N, A) = att2+att3 (+bt+bl)
__device__ float g_att  [N_ROWS * P_PIX];   // (N, P)

// ---------------------------------------------------------------------------
// Kernel 1: projection GEMMs, C = A @ B^T + bias   (B rows are K-major)
//   z=0: g_att1  = enc @ We^T + be                 (M=1024, N=256, K=512)
//   z=1: g_att23 = dh @ Wt^T + lo @ Wl^T + bt+bl   (M=1024, N=256, K=2x512)
// BM=64, BN=64, BK=16, 256 threads, 4x4 microtile.
// ---------------------------------------------------------------------------
__global__ __launch_bounds__(256)
void gemm_attproj(const float* __restrict__ enc, const float* __restrict__ We, const float* __restrict__ be,
                  const float* __restrict__ dh,  const float* __restrict__ Wt, const float* __restrict__ bt,
                  const float* __restrict__ lo,  const float* __restrict__ Wl, const float* __restrict__ bl)
{
    __shared__ float As[16][68];   // [k][m]
    __shared__ float Bs[16][68];   // [k][n]

    const int tid = threadIdx.x;
    const int z   = blockIdx.z;
    const int m0  = blockIdx.y * 64;
    const int n0  = blockIdx.x * 64;

    const int lk  = tid & 15;      // k lane
    const int lr  = tid >> 4;      // row group 0..15
    const int tn  = tid & 15;      // n micro (4)
    const int tm  = tid >> 4;      // m micro (4)

    float acc[4][4] = {};

    const int nseg = (z == 0) ? 1 : 2;
    for (int s = 0; s < nseg; s++) {
        const float* A = (z == 0) ? enc : (s == 0 ? dh : lo);
        const float* B = (z == 0) ? We  : (s == 0 ? Wt : Wl);
        for (int k0 = 0; k0 < E_DIM; k0 += 16) {
            __syncthreads();
            #pragma unroll
            for (int i = 0; i < 4; i++)
                As[lk][lr + 16 * i] = A[(m0 + lr + 16 * i) * E_DIM + k0 + lk];
            #pragma unroll
            for (int i = 0; i < 4; i++)
                Bs[lk][lr + 16 * i] = B[(n0 + lr + 16 * i) * E_DIM + k0 + lk];
            __syncthreads();

            #pragma unroll
            for (int kk = 0; kk < 16; kk++) {
                float4 ra = *(const float4*)&As[kk][tm * 4];
                float4 rb = *(const float4*)&Bs[kk][tn * 4];
                float a[4] = {ra.x, ra.y, ra.z, ra.w};
                float b[4] = {rb.x, rb.y, rb.z, rb.w};
                #pragma unroll
                for (int i = 0; i < 4; i++)
                    #pragma unroll
                    for (int j = 0; j < 4; j++)
                        acc[i][j] += a[i] * b[j];
            }
        }
    }

    float bias[4];
    #pragma unroll
    for (int j = 0; j < 4; j++) {
        int c = n0 + tn * 4 + j;
        bias[j] = (z == 0) ? be[c] : (bt[c] + bl[c]);
    }
    float* C = (z == 0) ? g_att1 : g_att23;
    #pragma unroll
    for (int i = 0; i < 4; i++) {
        float4 o = make_float4(acc[i][0] + bias[0], acc[i][1] + bias[1],
                               acc[i][2] + bias[2], acc[i][3] + bias[3]);
        *(float4*)&C[(m0 + tm * 4 + i) * A_DIM + n0 + tn * 4] = o;
    }
}

// ---------------------------------------------------------------------------
// Kernel 2: att[n,p] = sum_a relu(att1[p,a] + att23[n,a]) * Wf[a]
// (bf cancels in softmax). 64n x 64p tile, 256 threads, 4x4 microtile.
// ---------------------------------------------------------------------------
#define CA 64
__global__ __launch_bounds__(256)
void att_main_kernel(const float* __restrict__ Wf)
{
    __shared__ float s1 [CA][68];   // [a][p]
    __shared__ float s23[CA][68];   // [a][n]
    __shared__ float sw[A_DIM];

    const int tid = threadIdx.x;
    const int tx  = tid & 15;       // p micro (4)
    const int ty  = tid >> 4;       // n micro (4)
    const int p0  = blockIdx.x * 64;
    const int n0  = blockIdx.y * 64;

    if (tid < A_DIM) sw[tid] = Wf[tid];

    float acc[4][4] = {};           // [j:n][i:p]

    const int la = tid & 63;        // a within chunk
    const int lr = tid >> 6;        // 0..3

    for (int a0 = 0; a0 < A_DIM; a0 += CA) {
        __syncthreads();
        #pragma unroll
        for (int i = 0; i < 16; i++) {
            int r = lr + 4 * i;     // 0..63
            s1 [la][r] = g_att1 [(p0 + r) * A_DIM + a0 + la];
            s23[la][r] = g_att23[(n0 + r) * A_DIM + a0 + la];
        }
        __syncthreads();

        #pragma unroll 8
        for (int a = 0; a < CA; a++) {
            float wa = sw[a0 + a];
            float4 r1 = *(const float4*)&s1 [a][tx * 4];
            float4 r2 = *(const float4*)&s23[a][ty * 4];
            float x1[4] = {r1.x, r1.y, r1.z, r1.w};
            float x2[4] = {r2.x, r2.y, r2.z, r2.w};
            #pragma unroll
            for (int j = 0; j < 4; j++)
                #pragma unroll
                for (int i = 0; i < 4; i++)
                    acc[j][i] += fmaxf(x1[i] + x2[j], 0.0f) * wa;
        }
    }

    #pragma unroll
    for (int j = 0; j < 4; j++) {
        float4 o = make_float4(acc[j][0], acc[j][1], acc[j][2], acc[j][3]);
        *(float4*)&g_att[(n0 + ty * 4 + j) * P_PIX + p0 + tx * 4] = o;
    }
}

// ---------------------------------------------------------------------------
// Kernel 3: row softmax over P -> alpha
// ---------------------------------------------------------------------------
__global__ __launch_bounds__(256)
void softmax_kernel(float* __restrict__ alpha)
{
    const int n   = blockIdx.x;
    const int tid = threadIdx.x;
    const float* row = g_att + n * P_PIX;

    __shared__ float wred[8];
    __shared__ float bm, bs;

    float x[4];
    float m = -1e30f;
    #pragma unroll
    for (int i = 0; i < 4; i++) {
        x[i] = row[tid + 256 * i];
        m = fmaxf(m, x[i]);
    }
    #pragma unroll
    for (int o = 16; o > 0; o >>= 1) m = fmaxf(m, __shfl_xor_sync(0xffffffffu, m, o));
    if ((tid & 31) == 0) wred[tid >> 5] = m;
    __syncthreads();
    if (tid == 0) {
        float v = wred[0];
        #pragma unroll
        for (int k = 1; k < 8; k++) v = fmaxf(v, wred[k]);
        bm = v;
    }
    __syncthreads();
    m = bm;

    float s = 0.0f;
    #pragma unroll
    for (int i = 0; i < 4; i++) {
        x[i] = __expf(x[i] - m);
        s += x[i];
    }
    #pragma unroll
    for (int o = 16; o > 0; o >>= 1) s += __shfl_xor_sync(0xffffffffu, s, o);
    __syncthreads();
    if ((tid & 31) == 0) wred[tid >> 5] = s;
    __syncthreads();
    if (tid == 0) {
        float v = 0.0f;
        #pragma unroll
        for (int k = 0; k < 8; k++) v += wred[k];
        bs = v;
    }
    __syncthreads();
    float inv = 1.0f / bs;

    #pragma unroll
    for (int i = 0; i < 4; i++)
        alpha[n * P_PIX + tid + 256 * i] = x[i] * inv;
}

// ---------------------------------------------------------------------------
// Kernel 4: awe = alpha @ enc   (M=1024, N=512, K=1024)
// BM=64, BN=64, BK=16, 256 threads, 4x4 microtile. B is row-major [K][N].
// ---------------------------------------------------------------------------
__global__ __launch_bounds__(256)
void gemm_ab_v3(const float* __restrict__ A,   // alpha (N, P)
                const float* __restrict__ B,   // enc   (P, E)
                float* __restrict__ C)         // awe   (N, E)
{
    __shared__ float As[16][68];   // [k][m]
    __shared__ float Bs[16][68];   // [k][n]

    const int tid = threadIdx.x;
    const int m0  = blockIdx.y * 64;
    const int n0  = blockIdx.x * 64;

    const int lk  = tid & 15;      // A loader: k lane
    const int lr  = tid >> 4;      // A loader: row group
    const int bk  = tid >> 4;      // B loader: k (0..15)
    const int bn  = (tid & 15) * 4;// B loader: n chunk

    const int tn  = tid & 15;
    const int tm  = tid >> 4;

    float acc[4][4] = {};

    for (int k0 = 0; k0 < P_PIX; k0 += 16) {
        __syncthreads();
        #pragma unroll
        for (int i = 0; i < 4; i++)
            As[lk][lr + 16 * i] = A[(m0 + lr + 16 * i) * P_PIX + k0 + lk];
        {
            float4 bv = *(const float4*)&B[(k0 + bk) * E_DIM + n0 + bn];
            *(float4*)&Bs[bk][bn] = bv;
        }
        __syncthreads();

        #pragma unroll
        for (int kk = 0; kk < 16; kk++) {
            float4 ra = *(const float4*)&As[kk][tm * 4];
            float4 rb = *(const float4*)&Bs[kk][tn * 4];
            float a[4] = {ra.x, ra.y, ra.z, ra.w};
            float b[4] = {rb.x, rb.y, rb.z, rb.w};
            #pragma unroll
            for (int i = 0; i < 4; i++)
                #pragma unroll
                for (int j = 0; j < 4; j++)
                    acc[i][j] += a[i] * b[j];
        }
    }

    #pragma unroll
    for (int i = 0; i < 4; i++) {
        float4 o = make_float4(acc[i][0], acc[i][1], acc[i][2], acc[i][3]);
        *(float4*)&C[(m0 + tm * 4 + i) * E_DIM + n0 + tn * 4] = o;
    }
}

// ---------------------------------------------------------------------------
// Launch
// ---------------------------------------------------------------------------
extern "C" void kernel_launch(void* const* d_in, const int* in_sizes, int n_in,
                              void* d_out, int out_size)
{
    (void)in_sizes; (void)n_in; (void)out_size;
    const float* enc = (const float*)d_in[0];
    const float* dh  = (const float*)d_in[1];
    const float* lo  = (const float*)d_in[2];
    const float* We  = (const float*)d_in[3];
    const float* be  = (const float*)d_in[4];
    const float* Wt  = (const float*)d_in[5];
    const float* bt  = (const float*)d_in[6];
    const float* Wl  = (const float*)d_in[7];
    const float* bl  = (const float*)d_in[8];
    const float* Wf  = (const float*)d_in[9];
    // d_in[10] = bf: uniform shift, cancels in softmax.

    float* awe   = (float*)d_out;
    float* alpha = (float*)d_out + N_ROWS * E_DIM;

    dim3 g1(A_DIM / 64, 1024 / 64, 2);
    gemm_attproj<<<g1, 256>>>(enc, We, be, dh, Wt, bt, lo, Wl, bl);

    dim3 g2(P_PIX / 64, N_ROWS / 64);
    att_main_kernel<<<g2, 256>>>(Wf);

    softmax_kernel<<<N_ROWS, 256>>>(alpha);

    dim3 g4(E_DIM / 64, N_ROWS / 64);
    gemm_ab_v3<<<g4, 256>>>(alpha, enc, awe);
}